// round 15
// baseline (speedup 1.0000x reference)
#include <cuda_runtime.h>
#include <cuda_bf16.h>
#include <stdint.h>

// ---------------- problem constants ----------------
#define HID    256
#define GEO    13
#define DIN    781
#define NBR    4
#define DEPTHL 3
#define EPSB   1e-5f
#define E_CAP  100000

// ---------------- tiling ----------------
#define TM    128
#define NTH   512
#define NGRP0 25                      // layer-0 k32 groups (25*32 = 800 >= 781)
#define NGRPH 8                       // k32 groups per hidden layer
#define NGRPT (NGRP0 + DEPTHL*NGRPH)  // 49 k32 groups per branch
#define NSUB  (NGRPT*2)               // 98 k16 subgroups
#define KPAD0 (NGRP0*32)              // 800
#define KPB   (NSUB*16)               // 1568
#define SUB_ELEMS 4096                // per k16 subgroup per plane: 16 ntiles x 32 rows x 8 bf16

// ---------------- smem offsets (bytes) ----------------
#define OFF_SI 0
#define OFF_SJ 512
#define OFF_SK 1024
#define OFF_SE 1536
#define OFF_H  2048                   // hi plane 64KB + lo plane 64KB
#define OFF_B  (OFF_H + 131072)       // 3 stages x 32KB
#define SMEM_BYTES (OFF_B + 98304)    // 231424 (<= 227KB opt-in), 1 CTA/SM
// Layer-0 aliases inside H (dead during layer-0 mainloop):
//   X slots: OFF_H + slot*16384, slot = kc&1 (hi 8KB: 2 ksub x 4KB; lo at +8192)
#define OFF_RAW (OFF_H + 32768)       //   raw f32 ring: 3 slots x 16KB

__device__ int g_cnt[NBR];
__device__ int g_list[NBR * E_CAP];
// packed ldmatrix-native weights: [br][k16 subgroup][ntile][32 rows][8 bf16]
__device__ __align__(16) __nv_bfloat16 g_Whi[NBR * NSUB * SUB_ELEMS];
__device__ __align__(16) __nv_bfloat16 g_Wlo[NBR * NSUB * SUB_ELEMS];
// pre-folded BN: scale & shift per [br][layer][col]
__device__ __align__(16) float g_bnS[NBR * (DEPTHL + 1) * HID];
__device__ __align__(16) float g_bnH[NBR * (DEPTHL + 1) * HID];

// ---------------- helpers ----------------
__device__ __forceinline__ uint32_t smem_u32(const void* p) {
    uint32_t a;
    asm("{ .reg .u64 t; cvta.to.shared.u64 t, %1; cvt.u32.u64 %0, t; }" : "=r"(a) : "l"(p));
    return a;
}
__device__ __forceinline__ void cp16(uint32_t dst, const void* src) {
    asm volatile("cp.async.cg.shared.global [%0], [%1], 16;" :: "r"(dst), "l"(src) : "memory");
}
#define CP_COMMIT() asm volatile("cp.async.commit_group;" ::: "memory")
template<int N> __device__ __forceinline__ void cp_wait() {
    asm volatile("cp.async.wait_group %0;" :: "n"(N) : "memory");
}
__device__ __forceinline__ void ldsm4(uint32_t* r, uint32_t a) {
    asm volatile("ldmatrix.sync.aligned.m8n8.x4.shared.b16 {%0,%1,%2,%3}, [%4];"
        : "=r"(r[0]), "=r"(r[1]), "=r"(r[2]), "=r"(r[3]) : "r"(a));
}
__device__ __forceinline__ void mma16816(float* c, const uint32_t* a, const uint32_t* b) {
    asm volatile("mma.sync.aligned.m16n8k16.row.col.f32.bf16.bf16.f32 "
        "{%0,%1,%2,%3}, {%4,%5,%6,%7}, {%8,%9}, {%0,%1,%2,%3};"
        : "+f"(c[0]), "+f"(c[1]), "+f"(c[2]), "+f"(c[3])
        : "r"(a[0]), "r"(a[1]), "r"(a[2]), "r"(a[3]), "r"(b[0]), "r"(b[1]));
}
// bf16 hi/lo split of two floats, packed
__device__ __forceinline__ void cvt2(float a, float b, uint32_t& h, uint32_t& l) {
    __nv_bfloat16 ha = __float2bfloat16(a), hb = __float2bfloat16(b);
    __nv_bfloat16 la = __float2bfloat16(a - __bfloat162float(ha));
    __nv_bfloat16 lb = __float2bfloat16(b - __bfloat162float(hb));
    h = (uint32_t)__bfloat16_as_ushort(ha) | ((uint32_t)__bfloat16_as_ushort(hb) << 16);
    l = (uint32_t)__bfloat16_as_ushort(la) | ((uint32_t)__bfloat16_as_ushort(lb) << 16);
}

// ---------------- fused prep kernel ----------------
#define NW (NBR * KPB * HID)
__global__ void prep_all(const float* __restrict__ W0, const float* __restrict__ Wh,
                         const float* __restrict__ b0, const float* __restrict__ bh,
                         const float* __restrict__ gamma, const float* __restrict__ beta,
                         const float* __restrict__ rmean, const float* __restrict__ rvar,
                         float* __restrict__ out, int out_size) {
    int t = blockIdx.x * blockDim.x + threadIdx.x;

    if (t < NBR) g_cnt[t] = 0;

    {   // zero output (8 floats per thread)
        int base = t * 8;
        if (base + 8 <= out_size) {
            float4 z = make_float4(0.f, 0.f, 0.f, 0.f);
            *(float4*)(out + base)     = z;
            *(float4*)(out + base + 4) = z;
        } else {
            for (int i = base; i < out_size; i++) out[i] = 0.f;
        }
    }

    if (t < NBR * (DEPTHL + 1) * HID) {
        int c = t & 255;
        int rem = t >> 8;
        int layer = rem % (DEPTHL + 1);
        int br = rem / (DEPTHL + 1);
        float sc = gamma[t] * rsqrtf(rvar[t] + EPSB);
        float bias = (layer == 0) ? b0[br * HID + c]
                                  : bh[(size_t)(br * DEPTHL + layer - 1) * HID + c];
        g_bnS[t] = sc;
        g_bnH[t] = beta[t] - rmean[t] * sc + bias * sc;
    }

    if (t < NW) {
        int n = t & 255;
        int rem = t >> 8;
        int k = rem % KPB;
        int br = rem / KPB;
        float w;
        if (k < KPAD0) {
            w = (k < DIN) ? W0[((size_t)br * DIN + k) * HID + n] : 0.f;
        } else {
            int kk = k - KPAD0;
            int l = kk >> 8, k2 = kk & 255;
            w = Wh[(((size_t)(br * DEPTHL + l)) * HID + k2) * HID + n];
        }
        int gs = k >> 4;
        int kl = k & 15;
        int kh = kl >> 3, kb = kl & 7;
        int lrow = (n & 7) + ((n >> 3) & 1) * 16 + kh * 8;
        int ntile = n >> 4;
        size_t off = (((size_t)(br * NSUB + gs)) * 16 + ntile) * 256 + lrow * 8 + kb;
        __nv_bfloat16 h = __float2bfloat16(w);
        g_Whi[off] = h;
        g_Wlo[off] = __float2bfloat16(w - __bfloat162float(h));
    }
}

__global__ void bucket_kernel(const int* __restrict__ edx_ij,
                              const int* __restrict__ edx_jk,
                              const int* __restrict__ nei, int E) {
    int e = blockIdx.x * blockDim.x + threadIdx.x;
    if (e >= E) return;
    int Ein = *nei;
    int br = ((edx_ij[e] < Ein) ? 0 : 2) + ((edx_jk[e] < Ein) ? 0 : 1);
    int pos = atomicAdd(&g_cnt[br], 1);
    g_list[br * E_CAP + pos] = e;
}

// ---------------- main-kernel device helpers ----------------
// prefetch one k32 B group g (2 k16 subgroups, hi+lo) into ring stage
__device__ __forceinline__ void prefetch_B(uint32_t smb, int stage, int br, int g, int tid) {
    uint32_t d = smb + OFF_B + stage * 32768;
    #pragma unroll
    for (int s = 0; s < 2; s++) {
        size_t base = (size_t)(br * NSUB + 2 * g + s) * SUB_ELEMS;   // bf16 elems
        const char* sh = (const char*)(g_Whi + base) + tid * 16;
        const char* sl = (const char*)(g_Wlo + base) + tid * 16;
        cp16(d + s * 16384 + (uint32_t)tid * 16,        sh);
        cp16(d + s * 16384 + 8192 + (uint32_t)tid * 16, sl);
    }
}

// cp.async raw f32 node chunk c (1..23) into raw ring slot c%3.
// chunk c covers segment c/8, cols (c%8)*32 .. +32
__device__ __forceinline__ void cp_raw(uint32_t smb, int c, const float* __restrict__ nf,
                                       const int* sI, const int* sJ, const int* sK, int tid) {
    int r = tid >> 2, q = tid & 3;
    int seg = c >> 3;
    int idx = (seg == 0) ? sI[r] : (seg == 1) ? sJ[r] : sK[r];
    const float* src = nf + (size_t)idx * HID + (c & 7) * 32 + q * 4;
    uint32_t dst = smb + OFF_RAW + (c % 3) * 16384 + (uint32_t)(r * 128 + q * 16);
    cp16(dst,      src);
    cp16(dst + 64, src + 16);
}

// Write quad (r, q, ksub) of X slot in ldmatrix-native order.
__device__ __forceinline__ void write_X(char* sm, int slot, int ksub, int r, int q,
                                        float x0, float x1, float x2, float x3) {
    uint32_t h0, l0, h1, l1;
    cvt2(x0, x1, h0, l0);
    cvt2(x2, x3, h1, l1);
    int lrow = (r & 7) + ((r >> 3) & 1) * 8 + (q >> 1) * 16;
    uint32_t off = (uint32_t)((r >> 4) * 512 + lrow * 16 + (q & 1) * 8);
    char* base = sm + OFF_H + slot * 16384 + ksub * 4096;
    *(uint2*)(base + off)        = make_uint2(h0, h1);
    *(uint2*)(base + 8192 + off) = make_uint2(l0, l1);
}

// cvt node chunk c (1..23) from raw ring -> X slot (c&1)
__device__ __forceinline__ void cvt_X(char* sm, int c, int tid) {
    int r = tid >> 2, q = tid & 3;
    const char* raw = sm + OFF_RAW + (c % 3) * 16384 + r * 128;
    #pragma unroll
    for (int half = 0; half < 2; half++) {
        float4 v = *(const float4*)(raw + half * 64 + q * 16);
        write_X(sm, c & 1, half, r, q, v.x, v.y, v.z, v.w);
    }
}

// direct-gmem staging: group 0 (node cols 0..31) or group 24 (geo + pad)
__device__ __forceinline__ void stage_X_direct(char* sm, int g,
                                               const float* __restrict__ nf,
                                               const float* __restrict__ geo,
                                               const int* sI, const int* sE, int tid) {
    int r = tid >> 2, q = tid & 3;
    if (g == 0) {
        const float* src = nf + (size_t)sI[r] * HID;
        #pragma unroll
        for (int half = 0; half < 2; half++) {
            float4 v = *(const float4*)(src + half * 16 + q * 4);
            write_X(sm, 0, half, r, q, v.x, v.y, v.z, v.w);
        }
    } else {
        int e = sE[r];
        int c0 = q * 4;   // within k16 subchunk 0: global cols 768 + c0
        float x0 = (c0     < GEO) ? geo[(size_t)e * GEO + c0]     : 0.f;
        float x1 = (c0 + 1 < GEO) ? geo[(size_t)e * GEO + c0 + 1] : 0.f;
        float x2 = (c0 + 2 < GEO) ? geo[(size_t)e * GEO + c0 + 2] : 0.f;
        float x3 = (c0 + 3 < GEO) ? geo[(size_t)e * GEO + c0 + 3] : 0.f;
        write_X(sm, g & 1, 0, r, q, x0, x1, x2, x3);
        write_X(sm, g & 1, 1, r, q, 0.f, 0.f, 0.f, 0.f);
    }
}

// ---------------- main kernel ----------------
__global__ void __launch_bounds__(NTH, 1)
spnn_mma_kernel(const float* __restrict__ nf,
                const float* __restrict__ geo,
                const int*   __restrict__ ei,
                const float* __restrict__ att,
                float* __restrict__ out,
                int E)
{
    const int br  = blockIdx.y;
    const int cnt = g_cnt[br];
    const int m0  = blockIdx.x * TM;
    if (m0 >= cnt) return;

    extern __shared__ char sm[];
    const int tid = threadIdx.x;
    const int wid = tid >> 5, lid = tid & 31;
    const int wm = wid & 3, wn = wid >> 2;   // 4 m-warps x 4 n-warps

    int* sI = (int*)(sm + OFF_SI);
    int* sJ = (int*)(sm + OFF_SJ);
    int* sK = (int*)(sm + OFF_SK);
    int* sE = (int*)(sm + OFF_SE);

    const uint32_t smb = smem_u32(sm);

    if (tid < TM) {
        int idx = m0 + tid;
        int e = (idx < cnt) ? g_list[br * E_CAP + idx] : g_list[br * E_CAP];
        sE[tid] = e;
        sI[tid] = ei[e];
        sJ[tid] = ei[E + e];
        sK[tid] = ei[2 * E + e];
    }
    __syncthreads();     // indices visible

    // prologue: 2 commit groups in flight
    prefetch_B(smb, 0, br, 0, tid);
    cp_raw(smb, 1, nf, sI, sJ, sK, tid);
    CP_COMMIT();                              // {B0, raw1}
    prefetch_B(smb, 1, br, 1, tid);
    cp_raw(smb, 2, nf, sI, sJ, sK, tid);
    CP_COMMIT();                              // {B1, raw2}
    stage_X_direct(sm, 0, nf, geo, sI, sE, tid);   // X slot 0

    float acc[2][8][4];
    #pragma unroll
    for (int mt = 0; mt < 2; mt++)
        #pragma unroll
        for (int nt = 0; nt < 8; nt++)
            #pragma unroll
            for (int q = 0; q < 4; q++) acc[mt][nt][q] = 0.f;

    int gG = 0;   // global k32 group index

    #pragma unroll 1
    for (int layer = 0; layer <= DEPTHL; layer++) {
        const int ngrp = (layer == 0) ? NGRP0 : NGRPH;

        #pragma unroll 1
        for (int kc = 0; kc < ngrp; kc++) {
            cp_wait<1>();
            __syncthreads();

            // layer-0: produce X slot for the NEXT group
            if (layer == 0) {
                if (kc + 1 <= 23)      cvt_X(sm, kc + 1, tid);
                else if (kc + 1 == 24) stage_X_direct(sm, 24, nf, geo, sI, sE, tid);
            }

            // one commit group per iteration
            if (gG + 2 < NGRPT)
                prefetch_B(smb, (gG + 2) % 3, br, gG + 2, tid);
            if (layer == 0 && kc + 3 <= 23)
                cp_raw(smb, kc + 3, nf, sI, sJ, sK, tid);
            CP_COMMIT();

            uint32_t bStage = smb + OFF_B + (uint32_t)((gG % 3) * 32768);

            #pragma unroll
            for (int ksub = 0; ksub < 2; ksub++) {
                // A fragments
                uint32_t aH, aL;
                if (layer == 0) {
                    aH = smb + OFF_H + (uint32_t)((kc & 1) * 16384 + ksub * 4096);
                    aL = aH + 8192;
                } else {
                    aH = smb + OFF_H + (uint32_t)((kc * 2 + ksub) * 4096);
                    aL = aH + 65536;
                }
                uint32_t ahi[2][4], alo[2][4];
                #pragma unroll
                for (int mt = 0; mt < 2; mt++) {
                    uint32_t off = (uint32_t)((wm * 2 + mt) * 512 + lid * 16);
                    ldsm4(ahi[mt], aH + off);
                    ldsm4(alo[mt], aL + off);
                }

                uint32_t bB = bStage + (uint32_t)(ksub * 16384);
                #pragma unroll
                for (int ntp = 0; ntp < 4; ntp++) {
                    uint32_t off = (uint32_t)((wn * 4 + ntp) * 512 + lid * 16);
                    uint32_t bh4[4], bl4[4];
                    ldsm4(bh4, bB + off);
                    ldsm4(bl4, bB + 8192 + off);
                    #pragma unroll
                    for (int mt = 0; mt < 2; mt++)
                        #pragma unroll
                        for (int s = 0; s < 2; s++) {
                            float* c = acc[mt][ntp * 2 + s];
                            mma16816(c, ahi[mt], bh4 + s * 2);
                            mma16816(c, alo[mt], bh4 + s * 2);
                            mma16816(c, ahi[mt], bl4 + s * 2);
                        }
                }
            }
            gG++;
        }

        __syncthreads();   // all reads of H/X done before epilogue writes H

        const bool fin = (layer == DEPTHL);
        const float* bnS = g_bnS + (size_t)(br * (DEPTHL + 1) + layer) * HID;
        const float* bnH = g_bnH + (size_t)(br * (DEPTHL + 1) + layer) * HID;
        float attb = fin ? att[br] : 0.f;

        #pragma unroll
        for (int mt = 0; mt < 2; mt++) {
            int r0 = wm * 32 + mt * 16 + (lid >> 2);
            int r1 = r0 + 8;
            #pragma unroll
            for (int nt = 0; nt < 8; nt++) {
                float* c = acc[mt][nt];
                int j0 = wn * 64 + nt * 8 + (lid & 3) * 2;
                float2 scv = *(const float2*)(bnS + j0);
                float2 shv = *(const float2*)(bnH + j0);
                float f00 = fmaxf(fmaf(c[0], scv.x, shv.x), 0.f);
                float f01 = fmaxf(fmaf(c[1], scv.y, shv.y), 0.f);
                float f10 = fmaxf(fmaf(c[2], scv.x, shv.x), 0.f);
                float f11 = fmaxf(fmaf(c[3], scv.y, shv.y), 0.f);
                c[0] = c[1] = c[2] = c[3] = 0.f;
                if (!fin) {
                    uint32_t hv0, lv0, hv1, lv1;
                    cvt2(f00, f01, hv0, lv0);
                    cvt2(f10, f11, hv1, lv1);
                    int kg = j0 >> 4, kh = (j0 >> 3) & 1;
                    int lr0 = (lid >> 2) + kh * 16;
                    uint32_t base = (uint32_t)(kg * 4096 + (wm * 2 + mt) * 512 + (j0 & 7) * 2);
                    uint32_t o0 = base + (uint32_t)(lr0 * 16);
                    uint32_t o1 = base + (uint32_t)((lr0 + 8) * 16);
                    *(uint32_t*)(sm + OFF_H + o0)         = hv0;
                    *(uint32_t*)(sm + OFF_H + 65536 + o0) = lv0;
                    *(uint32_t*)(sm + OFF_H + o1)         = hv1;
                    *(uint32_t*)(sm + OFF_H + 65536 + o1) = lv1;
                } else {
                    if (m0 + r0 < cnt) {
                        float* op = out + (size_t)sI[r0] * HID + j0;
                        atomicAdd(op,     f00 * attb);
                        atomicAdd(op + 1, f01 * attb);
                    }
                    if (m0 + r1 < cnt) {
                        float* op = out + (size_t)sI[r1] * HID + j0;
                        atomicAdd(op,     f10 * attb);
                        atomicAdd(op + 1, f11 * attb);
                    }
                }
            }
        }
        // next layer's first-group sync orders these writes vs. reads
    }
}

extern "C" void kernel_launch(void* const* d_in, const int* in_sizes, int n_in,
                              void* d_out, int out_size) {
    const float* nf  = (const float*)d_in[0];
    const float* geo = (const float*)d_in[1];
    const int*   ei  = (const int*)d_in[2];
    const int*   eij = (const int*)d_in[3];
    const int*   ejk = (const int*)d_in[4];
    const float* att = (const float*)d_in[5];
    const float* W0  = (const float*)d_in[6];
    const float* b0  = (const float*)d_in[7];
    const float* Wh  = (const float*)d_in[8];
    const float* bh  = (const float*)d_in[9];
    const float* gam = (const float*)d_in[10];
    const float* bet = (const float*)d_in[11];
    const float* rme = (const float*)d_in[12];
    const float* rva = (const float*)d_in[13];
    const int*   nei = (const int*)d_in[14];

    int E = in_sizes[3];
    if (E > E_CAP) E = E_CAP;
    float* out = (float*)d_out;

    int n_zero = (out_size + 7) / 8;
    int total = (NW > n_zero) ? NW : n_zero;
    prep_all<<<(total + 255) / 256, 256>>>(W0, Wh, b0, bh, gam, bet, rme, rva,
                                           out, out_size);
    bucket_kernel<<<(E + 255) / 256, 256>>>(eij, ejk, nei, E);

    cudaFuncSetAttribute(spnn_mma_kernel,
                         cudaFuncAttributeMaxDynamicSharedMemorySize, SMEM_BYTES);
    dim3 grid((E + TM - 1) / TM, NBR);
    spnn_mma_kernel<<<grid, NTH, SMEM_BYTES>>>(nf, geo, ei, att, out, E);
}

// round 16
// speedup vs baseline: 1.1509x; 1.1509x over previous
#include <cuda_runtime.h>
#include <cuda_bf16.h>
#include <stdint.h>

// ---------------- problem constants ----------------
#define HID    256
#define GEO    13
#define DIN    781
#define NBR    4
#define DEPTHL 3
#define EPSB   1e-5f
#define E_CAP  100000

// ---------------- tiling ----------------
#define TM    64
#define NTH   256
#define NG0   49                      // layer-0 k16 groups (49*16=784 >= 781)
#define KPAD0 (NG0*16)
#define NGH   16                      // k16 groups per hidden layer
#define NGT   (NG0 + DEPTHL*NGH)      // 97 groups per branch (linear)
#define KPB   (NGT*16)                // 1552
#define GRP_ELEMS 4096                // 16 ntiles x 32 rows x 8 bf16 per plane

// ---------------- smem offsets (bytes) ----------------
#define OFF_SI 0
#define OFF_SJ 256
#define OFF_SK 512
#define OFF_SE 768
#define OFF_H  1024                   // hi plane 32KB + lo plane 32KB
#define OFF_B  (OFF_H + 65536)        // 3 stages x 16KB (hi 8KB + lo 8KB)
#define SMEM_BYTES (OFF_B + 49152)    // 115712 -> 2 CTA/SM
// Layer-0 aliases inside H (dead during layer 0):
//   X bf16 slots: OFF_H + (kc&1)*4096            (2 x 4KB: hi 2KB + lo 2KB each)
#define OFF_RAW (OFF_H + 8192)        //   raw f32 ring: 4 slots x 4KB

__device__ int g_cnt[NBR];
__device__ int g_list[NBR * E_CAP];
// packed ldmatrix-native weights: [br][group][ntile][32 rows][8 bf16]
__device__ __align__(16) __nv_bfloat16 g_Whi[NBR * NGT * GRP_ELEMS];
__device__ __align__(16) __nv_bfloat16 g_Wlo[NBR * NGT * GRP_ELEMS];
// pre-folded BN: scale & shift per [br][layer][col]
__device__ __align__(16) float g_bnS[NBR * (DEPTHL + 1) * HID];
__device__ __align__(16) float g_bnH[NBR * (DEPTHL + 1) * HID];

// ---------------- helpers ----------------
__device__ __forceinline__ uint32_t smem_u32(const void* p) {
    uint32_t a;
    asm("{ .reg .u64 t; cvta.to.shared.u64 t, %1; cvt.u32.u64 %0, t; }" : "=r"(a) : "l"(p));
    return a;
}
__device__ __forceinline__ void cp16(uint32_t dst, const void* src) {
    asm volatile("cp.async.cg.shared.global [%0], [%1], 16;" :: "r"(dst), "l"(src) : "memory");
}
#define CP_COMMIT() asm volatile("cp.async.commit_group;" ::: "memory")
template<int N> __device__ __forceinline__ void cp_wait() {
    asm volatile("cp.async.wait_group %0;" :: "n"(N) : "memory");
}
__device__ __forceinline__ void ldsm4(uint32_t* r, uint32_t a) {
    asm volatile("ldmatrix.sync.aligned.m8n8.x4.shared.b16 {%0,%1,%2,%3}, [%4];"
        : "=r"(r[0]), "=r"(r[1]), "=r"(r[2]), "=r"(r[3]) : "r"(a));
}
__device__ __forceinline__ void mma16816(float* c, const uint32_t* a, const uint32_t* b) {
    asm volatile("mma.sync.aligned.m16n8k16.row.col.f32.bf16.bf16.f32 "
        "{%0,%1,%2,%3}, {%4,%5,%6,%7}, {%8,%9}, {%0,%1,%2,%3};"
        : "+f"(c[0]), "+f"(c[1]), "+f"(c[2]), "+f"(c[3])
        : "r"(a[0]), "r"(a[1]), "r"(a[2]), "r"(a[3]), "r"(b[0]), "r"(b[1]));
}
// bf16 hi/lo split of two floats, packed
__device__ __forceinline__ void cvt2(float a, float b, uint32_t& h, uint32_t& l) {
    __nv_bfloat16 ha = __float2bfloat16(a), hb = __float2bfloat16(b);
    __nv_bfloat16 la = __float2bfloat16(a - __bfloat162float(ha));
    __nv_bfloat16 lb = __float2bfloat16(b - __bfloat162float(hb));
    h = (uint32_t)__bfloat16_as_ushort(ha) | ((uint32_t)__bfloat16_as_ushort(hb) << 16);
    l = (uint32_t)__bfloat16_as_ushort(la) | ((uint32_t)__bfloat16_as_ushort(lb) << 16);
}

// ---------------- fused prep kernel (weights + BN + zero cnt + zero out) ----------------
#define NT_W (NBR * NGT * 16 * 32)    // one thread per (br, group, ntile, lrow); 8 k each
__global__ void prep_all(const float* __restrict__ W0, const float* __restrict__ Wh,
                         const float* __restrict__ b0, const float* __restrict__ bh,
                         const float* __restrict__ gamma, const float* __restrict__ beta,
                         const float* __restrict__ rmean, const float* __restrict__ rvar,
                         float* __restrict__ out, int out_size) {
    int t = blockIdx.x * blockDim.x + threadIdx.x;

    if (t < NBR) g_cnt[t] = 0;

    {   // zero output (8 floats per thread)
        int base = t * 8;
        if (base + 8 <= out_size) {
            float4 z = make_float4(0.f, 0.f, 0.f, 0.f);
            *(float4*)(out + base)     = z;
            *(float4*)(out + base + 4) = z;
        } else {
            for (int i = base; i < out_size; i++) out[i] = 0.f;
        }
    }

    if (t < NBR * (DEPTHL + 1) * HID) {
        int c = t & 255;
        int rem = t >> 8;
        int layer = rem % (DEPTHL + 1);
        int br = rem / (DEPTHL + 1);
        float sc = gamma[t] * rsqrtf(rvar[t] + EPSB);
        float bias = (layer == 0) ? b0[br * HID + c]
                                  : bh[(size_t)(br * DEPTHL + layer - 1) * HID + c];
        g_bnS[t] = sc;
        g_bnH[t] = beta[t] - rmean[t] * sc + bias * sc;
    }

    if (t < NT_W) {
        int lrow = t & 31;
        int rem = t >> 5;
        int ntile = rem & 15;
        rem >>= 4;
        int g = rem % NGT;
        int br = rem / NGT;
        int kh = (lrow >> 3) & 1;
        int n = (lrow & 7) | (((lrow >> 4) & 1) << 3) | (ntile << 4);
        int kbase = g * 16 + kh * 8;

        float w[8];
        #pragma unroll
        for (int p = 0; p < 8; p++) {
            int k = kbase + p;
            float v;
            if (k < KPAD0) {
                v = (k < DIN) ? W0[((size_t)br * DIN + k) * HID + n] : 0.f;
            } else {
                int kk = k - KPAD0;
                int l = kk >> 8, k2 = kk & 255;
                v = Wh[(((size_t)(br * DEPTHL + l)) * HID + k2) * HID + n];
            }
            w[p] = v;
        }
        uint32_t hi[4], lo[4];
        #pragma unroll
        for (int p = 0; p < 4; p++) cvt2(w[2*p], w[2*p + 1], hi[p], lo[p]);

        size_t off = (((size_t)(br * NGT + g)) * 16 + ntile) * 256 + lrow * 8;  // elems
        *(uint4*)(g_Whi + off) = make_uint4(hi[0], hi[1], hi[2], hi[3]);
        *(uint4*)(g_Wlo + off) = make_uint4(lo[0], lo[1], lo[2], lo[3]);
    }
}

__global__ void bucket_kernel(const int* __restrict__ edx_ij,
                              const int* __restrict__ edx_jk,
                              const int* __restrict__ nei, int E) {
    int e = blockIdx.x * blockDim.x + threadIdx.x;
    if (e >= E) return;
    int Ein = *nei;
    int br = ((edx_ij[e] < Ein) ? 0 : 2) + ((edx_jk[e] < Ein) ? 0 : 1);
    int pos = atomicAdd(&g_cnt[br], 1);
    g_list[br * E_CAP + pos] = e;
}

// ---------------- main-kernel device helpers ----------------
__device__ __forceinline__ void prefetch_B(uint32_t smb, int slot, int br, int g, int tid) {
    size_t base = (size_t)(br * NGT + g) * GRP_ELEMS;   // bf16 elems
    uint32_t d = smb + OFF_B + slot * 16384 + (uint32_t)tid * 16;
    const char* sh = (const char*)(g_Whi + base) + tid * 16;
    const char* sl = (const char*)(g_Wlo + base) + tid * 16;
    cp16(d,         sh);
    cp16(d + 4096,  sh + 4096);
    cp16(d + 8192,  sl);
    cp16(d + 12288, sl + 4096);
}

// cp.async one raw f32 node chunk c (1..47) into raw ring slot c&3.
__device__ __forceinline__ void cp_raw(uint32_t smb, int c, const float* __restrict__ nf,
                                       const int* sI, const int* sJ, const int* sK, int tid) {
    int r = tid >> 2, q = tid & 3;
    int seg = c >> 4;
    int idx = (seg == 0) ? sI[r] : (seg == 1) ? sJ[r] : sK[r];
    cp16(smb + OFF_RAW + (c & 3) * 4096 + (uint32_t)(r * 64 + q * 16),
         nf + (size_t)idx * HID + (c & 15) * 16 + q * 4);
}

// Write the (r, q) quad of chunk c into X bf16 slot (c&1) in ldmatrix-native order.
__device__ __forceinline__ void write_X(char* sm, int c, int r, int q,
                                        float x0, float x1, float x2, float x3) {
    uint32_t h0, l0, h1, l1;
    cvt2(x0, x1, h0, l0);
    cvt2(x2, x3, h1, l1);
    int kh = q >> 1;
    int lrow = (r & 7) + ((r >> 3) & 1) * 8 + kh * 16;
    uint32_t off = (uint32_t)((r >> 4) * 512 + lrow * 16 + (q & 1) * 8);
    char* slot = sm + OFF_H + (c & 1) * 4096;
    *(uint2*)(slot + off)        = make_uint2(h0, h1);
    *(uint2*)(slot + 2048 + off) = make_uint2(l0, l1);
}

// cvt chunk c (1..47) from raw ring -> X slot
__device__ __forceinline__ void cvt_X(char* sm, int c, int tid) {
    int r = tid >> 2, q = tid & 3;
    float4 v = *(const float4*)(sm + OFF_RAW + (c & 3) * 4096 + r * 64 + q * 16);
    write_X(sm, c, r, q, v.x, v.y, v.z, v.w);
}

// direct-gmem staging for chunk 0 (nodes) and chunk 48 (geo)
__device__ __forceinline__ void stage_X_direct(char* sm, int kc,
                                               const float* __restrict__ nf,
                                               const float* __restrict__ geo,
                                               const int* sI, const int* sE, int tid) {
    int r = tid >> 2, q = tid & 3;
    float x0, x1, x2, x3;
    if (kc == 0) {
        const float* src = nf + (size_t)sI[r] * HID + q * 4;
        float4 v = *(const float4*)src;
        x0 = v.x; x1 = v.y; x2 = v.z; x3 = v.w;
    } else {
        int e = sE[r];
        int c0 = q * 4;
        x0 = (c0     < GEO) ? geo[(size_t)e * GEO + c0]     : 0.f;
        x1 = (c0 + 1 < GEO) ? geo[(size_t)e * GEO + c0 + 1] : 0.f;
        x2 = (c0 + 2 < GEO) ? geo[(size_t)e * GEO + c0 + 2] : 0.f;
        x3 = (c0 + 3 < GEO) ? geo[(size_t)e * GEO + c0 + 3] : 0.f;
    }
    write_X(sm, kc, r, q, x0, x1, x2, x3);
}

// ---------------- main kernel ----------------
__global__ void __launch_bounds__(NTH, 2)
spnn_mma_kernel(const float* __restrict__ nf,
                const float* __restrict__ geo,
                const int*   __restrict__ ei,
                const float* __restrict__ att,
                float* __restrict__ out,
                int E)
{
    const int br  = blockIdx.y;
    const int cnt = g_cnt[br];
    const int m0  = blockIdx.x * TM;
    if (m0 >= cnt) return;

    extern __shared__ char sm[];
    const int tid = threadIdx.x;
    const int wid = tid >> 5, lid = tid & 31;
    const int wm = wid & 1, wn = wid >> 1;   // 2 m-warps x 4 n-warps

    int* sI = (int*)(sm + OFF_SI);
    int* sJ = (int*)(sm + OFF_SJ);
    int* sK = (int*)(sm + OFF_SK);
    int* sE = (int*)(sm + OFF_SE);

    const uint32_t smb = smem_u32(sm);

    if (tid < TM) {
        int idx = m0 + tid;
        int e = (idx < cnt) ? g_list[br * E_CAP + idx] : g_list[br * E_CAP];
        sE[tid] = e;
        sI[tid] = ei[e];
        sJ[tid] = ei[E + e];
        sK[tid] = ei[2 * E + e];
    }
    __syncthreads();     // indices visible for cp_raw / staging

    // prologue: exactly 2 commit groups in flight at loop entry
    prefetch_B(smb, 0, br, 0, tid);
    cp_raw(smb, 1, nf, sI, sJ, sK, tid);
    CP_COMMIT();                              // {B0, raw1}
    prefetch_B(smb, 1, br, 1, tid);
    cp_raw(smb, 2, nf, sI, sJ, sK, tid);
    CP_COMMIT();                              // {B1, raw2}
    stage_X_direct(sm, 0, nf, geo, sI, sE, tid);   // X slot 0

    float acc[2][8][4];
    #pragma unroll
    for (int mt = 0; mt < 2; mt++)
        #pragma unroll
        for (int nt = 0; nt < 8; nt++)
            #pragma unroll
            for (int q = 0; q < 4; q++) acc[mt][nt][q] = 0.f;

    int gidx = 0;

    #pragma unroll 1
    for (int layer = 0; layer <= DEPTHL; layer++) {
        const int nch = (layer == 0) ? NG0 : NGH;

        #pragma unroll 1
        for (int kc = 0; kc < nch; kc++) {
            cp_wait<1>();        // retires group committed 2 iterations ago
            __syncthreads();

            // 1) A fragments FIRST (tensor stream starts asap)
            uint32_t aH, aL;
            if (layer == 0) {
                aH = smb + OFF_H + (uint32_t)((kc & 1) * 4096);
                aL = aH + 2048;
            } else {
                aH = smb + OFF_H + (uint32_t)(kc * 2048);
                aL = aH + 32768;
            }
            uint32_t ahi[2][4], alo[2][4];
            #pragma unroll
            for (int mt = 0; mt < 2; mt++) {
                uint32_t off = (uint32_t)((wm * 2 + mt) * 512 + lid * 16);
                ldsm4(ahi[mt], aH + off);
                ldsm4(alo[mt], aL + off);
            }

            // 2) async prefetches (latency hides under MMA loop)
            if (gidx + 2 < NGT)
                prefetch_B(smb, (gidx + 2) % 3, br, gidx + 2, tid);
            if (layer == 0 && kc + 3 <= 47)
                cp_raw(smb, kc + 3, nf, sI, sJ, sK, tid);
            CP_COMMIT();

            // 3) B LDSM + MMA loop
            uint32_t bB = smb + OFF_B + (uint32_t)((gidx % 3) * 16384);
            #pragma unroll
            for (int ntp = 0; ntp < 4; ntp++) {
                uint32_t off = (uint32_t)((wn * 4 + ntp) * 512 + lid * 16);
                uint32_t bh4[4], bl4[4];
                ldsm4(bh4, bB + off);
                ldsm4(bl4, bB + 8192 + off);
                #pragma unroll
                for (int mt = 0; mt < 2; mt++)
                    #pragma unroll
                    for (int s = 0; s < 2; s++) {
                        float* c = acc[mt][ntp * 2 + s];
                        mma16816(c, ahi[mt], bh4 + s * 2);
                        mma16816(c, alo[mt], bh4 + s * 2);
                        mma16816(c, ahi[mt], bl4 + s * 2);
                    }
            }

            // 4) stage NEXT layer-0 X chunk at the END (ALU overlaps tensor drain).
            //    Safe: writes X slot (kc+1)&1 whose prior readers (iter kc-1)
            //    finished before this iteration's barrier; raw reads covered by
            //    this iteration's cp_wait.
            if (layer == 0) {
                if (kc + 1 <= 47)      cvt_X(sm, kc + 1, tid);
                else if (kc + 1 == 48) stage_X_direct(sm, 48, nf, geo, sI, sE, tid);
            }
            gidx++;
        }

        __syncthreads();   // all reads of H/X done before epilogue writes H

        const bool fin = (layer == DEPTHL);
        const float* bnS = g_bnS + (size_t)(br * (DEPTHL + 1) + layer) * HID;
        const float* bnH = g_bnH + (size_t)(br * (DEPTHL + 1) + layer) * HID;
        float attb = fin ? att[br] : 0.f;

        #pragma unroll
        for (int mt = 0; mt < 2; mt++) {
            int r0 = wm * 32 + mt * 16 + (lid >> 2);
            int r1 = r0 + 8;
            #pragma unroll
            for (int nt = 0; nt < 8; nt++) {
                float* c = acc[mt][nt];
                int j0 = wn * 64 + nt * 8 + (lid & 3) * 2;
                float2 scv = *(const float2*)(bnS + j0);
                float2 shv = *(const float2*)(bnH + j0);
                float f00 = fmaxf(fmaf(c[0], scv.x, shv.x), 0.f);
                float f01 = fmaxf(fmaf(c[1], scv.y, shv.y), 0.f);
                float f10 = fmaxf(fmaf(c[2], scv.x, shv.x), 0.f);
                float f11 = fmaxf(fmaf(c[3], scv.y, shv.y), 0.f);
                c[0] = c[1] = c[2] = c[3] = 0.f;
                if (!fin) {
                    uint32_t hv0, lv0, hv1, lv1;
                    cvt2(f00, f01, hv0, lv0);
                    cvt2(f10, f11, hv1, lv1);
                    int kg = j0 >> 4, kh = (j0 >> 3) & 1;
                    int lr0 = (lid >> 2) + kh * 16;
                    uint32_t base = (uint32_t)(kg * 2048 + (wm * 2 + mt) * 512 + (j0 & 7) * 2);
                    uint32_t o0 = base + (uint32_t)(lr0 * 16);
                    uint32_t o1 = base + (uint32_t)((lr0 + 8) * 16);
                    *(uint32_t*)(sm + OFF_H + o0)         = hv0;
                    *(uint32_t*)(sm + OFF_H + 32768 + o0) = lv0;
                    *(uint32_t*)(sm + OFF_H + o1)         = hv1;
                    *(uint32_t*)(sm + OFF_H + 32768 + o1) = lv1;
                } else {
                    if (m0 + r0 < cnt) {
                        float* op = out + (size_t)sI[r0] * HID + j0;
                        atomicAdd(op,     f00 * attb);
                        atomicAdd(op + 1, f01 * attb);
                    }
                    if (m0 + r1 < cnt) {
                        float* op = out + (size_t)sI[r1] * HID + j0;
                        atomicAdd(op,     f10 * attb);
                        atomicAdd(op + 1, f11 * attb);
                    }
                }
            }
        }
        // next layer's first-group sync orders these writes vs. reads
    }
}

extern "C" void kernel_launch(void* const* d_in, const int* in_sizes, int n_in,
                              void* d_out, int out_size) {
    const float* nf  = (const float*)d_in[0];
    const float* geo = (const float*)d_in[1];
    const int*   ei  = (const int*)d_in[2];
    const int*   eij = (const int*)d_in[3];
    const int*   ejk = (const int*)d_in[4];
    const float* att = (const float*)d_in[5];
    const float* W0  = (const float*)d_in[6];
    const float* b0  = (const float*)d_in[7];
    const float* Wh  = (const float*)d_in[8];
    const float* bh  = (const float*)d_in[9];
    const float* gam = (const float*)d_in[10];
    const float* bet = (const float*)d_in[11];
    const float* rme = (const float*)d_in[12];
    const float* rva = (const float*)d_in[13];
    const int*   nei = (const int*)d_in[14];

    int E = in_sizes[3];
    if (E > E_CAP) E = E_CAP;
    float* out = (float*)d_out;

    int n_zero = (out_size + 7) / 8;
    int total = (NT_W > n_zero) ? NT_W : n_zero;
    prep_all<<<(total + 255) / 256, 256>>>(W0, Wh, b0, bh, gam, bet, rme, rva,
                                           out, out_size);
    bucket_kernel<<<(E + 255) / 256, 256>>>(eij, ejk, nei, E);

    cudaFuncSetAttribute(spnn_mma_kernel,
                         cudaFuncAttributeMaxDynamicSharedMemorySize, SMEM_BYTES);
    dim3 grid((E + TM - 1) / TM, NBR);
    spnn_mma_kernel<<<grid, NTH, SMEM_BYTES>>>(nf, geo, ei, att, out, E);
}